// round 16
// baseline (speedup 1.0000x reference)
#include <cuda_runtime.h>
#include <cuda_fp16.h>
#include <math.h>

#define N    2048
#define HID  16
#define TPB  256
#define T    32
#define NT   (N / T)               // 64
#define NBLK (NT * (NT + 1) / 2)   // 2080

// Accumulators per row: {sum_e, sum_e*f0 .. sum_e*f7} — zeroed via cudaMemsetAsync
__device__ float g_acc[N * 9];

__device__ __forceinline__ float rcpa(float x) {
    float r; asm("rcp.approx.f32 %0, %1;" : "=f"(r) : "f"(x)); return r;
}
__device__ __forceinline__ float ex2a(float x) {
    float r; asm("ex2.approx.f32 %0, %1;" : "=f"(r) : "f"(x)); return r;
}
__device__ __forceinline__ float lg2a(float x) {
    float r; asm("lg2.approx.f32 %0, %1;" : "=f"(r) : "f"(x)); return r;
}
__device__ __forceinline__ __half2 tanh2a(__half2 x) {
    unsigned xi = *reinterpret_cast<unsigned*>(&x), ri;
    asm("tanh.approx.f16x2 %0, %1;" : "=r"(ri) : "r"(xi));
    return *reinterpret_cast<__half2*>(&ri);
}
__device__ __forceinline__ __half2 fh2(float f) {
    unsigned u = __float_as_uint(f);
    return *reinterpret_cast<__half2*>(&u);
}

// Compute the 7 per-signal derived scalars from raw params.
__device__ __forceinline__ void signal_pre(const float* __restrict__ pi, float out[7]) {
    float m1 = fmaf(pi[0], 95.f, 5.f);
    float m2 = fmaf(pi[1], 95.f, 5.f);
    float mc = ex2a(fmaf(0.6f, lg2a(m1 * m2), -0.2f * lg2a(m1 + m2)));
    out[0] = pi[5];                     // t
    out[1] = pi[3];                     // ra
    out[2] = pi[4];                     // dec
    out[3] = mc;                        // chirp mass
    out[4] = 220.f / (m1 + m2);         // f_isco
    out[5] = fmaf(pi[2], 2950.f, 50.f); // dist
    out[6] = pi[7];                     // psi
}

// ---------------------------------------------------------------------------
// Pair kernel: 32x32 tiles, triangular grid. Fully self-contained: computes
// per-signal scalars + packed weights in the block prologue, then the fused
// importance-net (fp16x2 GEMV + LN + tanh-GELU) exp(logit) and accumulates
// {e, e*f0..e*f7} into BOTH row-i and row-j accumulators.
// ---------------------------------------------------------------------------
__global__ __launch_bounds__(TPB) void pair_kernel(
    const float* __restrict__ params,
    const float* __restrict__ iw1, const float* __restrict__ ib1,
    const float* __restrict__ ig1, const float* __restrict__ ibt1,
    const float* __restrict__ iw2, const float* __restrict__ ib2)
{
    __shared__ __align__(16) __half2 s_wh[64];
    __shared__ __half2 s_bh[8], s_g2[8], s_bt2[8], s_w2h[8];
    __shared__ float   s_col[8];
    __shared__ float   s_bm;
    __shared__ float   s_ipre[7][T];
    __shared__ float   s_jpre[7][T];
    __shared__ float   s_jred[8][T][9];
    __shared__ float   s_row[T][16][9];   // [row][group][k], 18 KB

    const int tid  = threadIdx.x;
    const int lane = tid & 31;
    const int wg   = tid >> 5;

    // Triangular decode: blocks enumerate (ti, tj) with tj >= ti.
    int b = blockIdx.x;
    int ti = (int)((2.f * NT + 1.f - sqrtf((2.f * NT + 1.f) * (2.f * NT + 1.f) - 8.f * (float)b)) * 0.5f);
    if (ti >= NT) ti = NT - 1;
    while (ti > 0 && (ti * NT - ti * (ti - 1) / 2) > b) ti--;
    while (((ti + 1) * NT - (ti + 1) * ti / 2) <= b) ti++;
    const int tj = ti + (b - (ti * NT - ti * (ti - 1) / 2));
    const bool diag = (ti == tj);

    // ---- Prologue phase 1: weight col-means + per-signal scalars ----
    if (tid < 8) {
        float s = 0.f;
#pragma unroll
        for (int h = 0; h < HID; h++) s += iw1[h * 8 + tid];
        s_col[tid] = s * (1.f / HID);
    } else if (tid == 8) {
        float bm = 0.f;
#pragma unroll
        for (int h = 0; h < HID; h++) bm += ib1[h];
        s_bm = bm * (1.f / HID);
    }
    if (tid >= 32 && tid < 96) {
        int t = tid - 32;
        int local = t & 31;
        int sig = ((t < 32) ? ti * T : tj * T) + local;
        float pr[7];
        signal_pre(params + sig * 15, pr);
        float (*dst)[T] = (t < 32) ? s_ipre : s_jpre;
#pragma unroll
        for (int k = 0; k < 7; k++) dst[k][local] = pr[k];
    }
    __syncthreads();

    // ---- Prologue phase 2: pack weights into smem (fp16x2) ----
    if (tid < 64) {
        int hp = tid & 7, k = tid >> 3;
        s_wh[tid] = __floats2half2_rn(iw1[hp * 8 + k]       - s_col[k],
                                      iw1[(hp + 8) * 8 + k] - s_col[k]);
    } else if (tid < 72) {
        int h = tid - 64;
        s_bh[h] = __floats2half2_rn(ib1[h] - s_bm, ib1[h + 8] - s_bm);
    } else if (tid < 80) {
        int h = tid - 72;
        s_g2[h] = __floats2half2_rn(ig1[h], ig1[h + 8]);
    } else if (tid < 88) {
        int h = tid - 80;
        s_bt2[h] = __floats2half2_rn(ibt1[h], ibt1[h + 8]);
    } else if (tid < 96) {
        int h = tid - 88;
        s_w2h[h] = __floats2half2_rn(0.5f * iw2[h], 0.5f * iw2[h + 8]);
    }

    const float lg0 = ib2[0];
    const __half2 TA2  = __float2half2_rn(0.7978845608f);   // sqrt(2/pi)
    const __half2 TB2  = __float2half2_rn(0.035677408f);    // TA * 0.044715
    const __half2 ONE2 = __float2half2_rn(1.f);

    __syncthreads();

    // j-side scalars into registers for the whole block
    const float tj_ = s_jpre[0][lane], raj = s_jpre[1][lane], dej = s_jpre[2][lane];
    const float mcj = s_jpre[3][lane], fij = s_jpre[4][lane], dij = s_jpre[5][lane];
    const float psj = s_jpre[6][lane];
    const int j = tj * T + lane;

    float jacc[9];
#pragma unroll
    for (int k = 0; k < 9; k++) jacc[k] = 0.f;

#pragma unroll
    for (int m = 0; m < 4; m++) {
        const int r = (m << 3) + wg;
        float v[9];
        const bool valid = (!diag) || (j > ti * T + r);
        if (valid) {
            const float ti_ = s_ipre[0][r], rai = s_ipre[1][r], dei = s_ipre[2][r];
            const float mci = s_ipre[3][r], fii = s_ipre[4][r], dii = s_ipre[5][r];
            const float psi = s_ipre[6][r];

            float dra = fabsf(rai - raj);
            float dde = fabsf(dei - dej);
            float f0 = fabsf(ti_ - tj_);
            float ss = fmaxf(fmaf(dra, dra, dde * dde), 1e-30f);
            float f1 = ss * rsqrtf(ss);
            float f2 = rcpa(fmaf(fabsf(mci - mcj), (1.f / 30.f), 1.f));
            float f3 = ex2a(-fabsf(fii - fij) * 0.0144269504f);
            float f4 = fminf(dii, dij) * rcpa(fmaxf(dii, dij));
            float f5 = fabsf(psi - psj);

            // ---- fp16x2 GEMV: acc[hp] = {z[hp], z[hp+8]} ----
            float fk[8] = {f0, f1, f2, f3, f4, f5, dra, dde};
            __half2 acc[8];
#pragma unroll
            for (int hp = 0; hp < 8; hp++) acc[hp] = s_bh[hp];
            const float4* wh4 = reinterpret_cast<const float4*>(s_wh);
#pragma unroll
            for (int k = 0; k < 8; k++) {
                __half2 hf = __float2half2_rn(fk[k]);
                float4 wa = wh4[k * 2 + 0];
                float4 wb = wh4[k * 2 + 1];
                acc[0] = __hfma2(fh2(wa.x), hf, acc[0]);
                acc[1] = __hfma2(fh2(wa.y), hf, acc[1]);
                acc[2] = __hfma2(fh2(wa.z), hf, acc[2]);
                acc[3] = __hfma2(fh2(wa.w), hf, acc[3]);
                acc[4] = __hfma2(fh2(wb.x), hf, acc[4]);
                acc[5] = __hfma2(fh2(wb.y), hf, acc[5]);
                acc[6] = __hfma2(fh2(wb.z), hf, acc[6]);
                acc[7] = __hfma2(fh2(wb.w), hf, acc[7]);
            }
            // ---- variance (half2 -> fp32 finish) ----
            __half2 var2 = __float2half2_rn(0.f);
#pragma unroll
            for (int hp = 0; hp < 8; hp++) var2 = __hfma2(acc[hp], acc[hp], var2);
            float2 vf = __half22float2(var2);
            float inv = rsqrtf(fmaf(vf.x + vf.y, (1.f / HID), 1e-5f));
            __half2 inv2 = __float2half2_rn(inv);

            // ---- fp16x2 LN + tanh-GELU epilogue ----
            __half2 lg2 = __float2half2_rn(0.f);
#pragma unroll
            for (int hp = 0; hp < 8; hp++) {
                __half2 xn = __hfma2(__hmul2(acc[hp], inv2), s_g2[hp], s_bt2[hp]);
                __half2 x2 = __hmul2(xn, xn);
                __half2 ar = __hmul2(xn, __hfma2(TB2, x2, TA2));
                __half2 th = tanh2a(ar);
                __half2 hw = __hmul2(s_w2h[hp], xn);
                lg2 = __hfma2(hw, __hadd2(ONE2, th), lg2);
            }
            float2 lf = __half22float2(lg2);
            float lg = lg0 + lf.x + lf.y;
            float e = ex2a(lg * 1.44269504088896f);

            v[0] = e;
            v[1] = e * f0; v[2] = e * f1; v[3] = e * f2; v[4] = e * f3;
            v[5] = e * f4; v[6] = e * f5; v[7] = e * dra; v[8] = e * dde;
#pragma unroll
            for (int k = 0; k < 9; k++) jacc[k] += v[k];
        } else {
#pragma unroll
            for (int k = 0; k < 9; k++) v[k] = 0.f;
        }
        // Row-side: 1-step butterfly -> lanes 0-15 hold 16 disjoint group sums;
        // plain stores into this row's private smem slot (written exactly once).
#pragma unroll
        for (int k = 0; k < 9; k++) {
            float x = v[k] + __shfl_xor_sync(0xFFFFFFFFu, v[k], 16);
            if (lane < 16) s_row[r][lane][k] = x;
        }
    }

    // Col-side staging
#pragma unroll
    for (int k = 0; k < 9; k++) s_jred[wg][lane][k] = jacc[k];
    __syncthreads();

    // Row-side finish: 288 (r,k) items, strided so ALL are covered.
    for (int it = tid; it < T * 9; it += TPB) {
        int r = it / 9, k = it - r * 9;
        float s = 0.f;
#pragma unroll
        for (int g = 0; g < 16; g++) s += s_row[r][g][k];
        atomicAdd(&g_acc[(size_t)(ti * T + r) * 9 + k], s);
    }
    // Col-side finish: threads 0-31, one column each.
    if (tid < T) {
        const int jj = tj * T + tid;
#pragma unroll
        for (int k = 0; k < 9; k++) {
            float s = 0.f;
#pragma unroll
            for (int w = 0; w < 8; w++) s += s_jred[w][tid][k];
            atomicAdd(&g_acc[(size_t)jj * 9 + k], s);
        }
    }
}

// ---------------------------------------------------------------------------
// Final: normalize + overlap net. One warp per row.
// ---------------------------------------------------------------------------
__global__ __launch_bounds__(TPB) void final_kernel(
    const float* __restrict__ ow1, const float* __restrict__ ob1,
    const float* __restrict__ og1, const float* __restrict__ obt1,
    const float* __restrict__ ow2, const float* __restrict__ ob2,
    float* __restrict__ out)
{
    __shared__ float s_h2[8][32];
    const int tid  = threadIdx.x;
    const int lane = tid & 31;
    const int wid  = tid >> 5;
    const int row  = blockIdx.x * 8 + wid;

    float myv = (lane < 9) ? g_acc[(size_t)row * 9 + lane] : 0.f;
    float invS = rcpa(__shfl_sync(0xFFFFFFFFu, myv, 0));

    float a = ob1[lane];
#pragma unroll
    for (int f = 0; f < 8; f++)
        a = fmaf(ow1[lane * 8 + f], __shfl_sync(0xFFFFFFFFu, myv, f + 1) * invS, a);

    float s = a;
#pragma unroll
    for (int o = 16; o; o >>= 1) s += __shfl_xor_sync(0xFFFFFFFFu, s, o);
    float mu = s * (1.f / 32.f);
    float d = a - mu;
    float v = d * d;
#pragma unroll
    for (int o = 16; o; o >>= 1) v += __shfl_xor_sync(0xFFFFFFFFu, v, o);
    float invs = rsqrtf(fmaf(v, (1.f / 32.f), 1e-5f));
    float xn = fmaf(d * invs, og1[lane], obt1[lane]);

    // accurate 4-term erf GELU (only 32 lanes/row — cost irrelevant)
    float ax = fabsf(xn) * 0.70710678118654752f;
    float u  = rcpa(fmaf(0.3275911f, ax, 1.f));
    float pl = fmaf(fmaf(fmaf(fmaf(1.061405429f, u, -1.453152027f),
                               u, 1.421413741f),
                          u, -0.284496736f),
                     u, 0.254829592f) * u;
    float e_ = ex2a(-1.44269504088896f * (ax * ax));
    float er = fmaf(-pl, e_, 1.f);
    er = copysignf(er, xn);
    s_h2[wid][lane] = 0.5f * xn * (1.f + er);
    __syncwarp();

    if (lane < 16) {
        float o_ = ob2[lane];
#pragma unroll
        for (int k = 0; k < 32; k++) o_ = fmaf(ow2[lane * 32 + k], s_h2[wid][k], o_);
        out[row * 16 + lane] = o_;
    }
}

extern "C" void kernel_launch(void* const* d_in, const int* in_sizes, int n_in,
                              void* d_out, int out_size) {
    const float* params = (const float*)d_in[0];
    const float* iw1  = (const float*)d_in[1];
    const float* ib1  = (const float*)d_in[2];
    const float* ig1  = (const float*)d_in[3];
    const float* ibt1 = (const float*)d_in[4];
    const float* iw2  = (const float*)d_in[5];
    const float* ib2  = (const float*)d_in[6];
    const float* ow1  = (const float*)d_in[7];
    const float* ob1  = (const float*)d_in[8];
    const float* og1  = (const float*)d_in[9];
    const float* obt1 = (const float*)d_in[10];
    const float* ow2  = (const float*)d_in[11];
    const float* ob2  = (const float*)d_in[12];
    float* out = (float*)d_out;

    // Zero the accumulators with a memset node (replaces the pre kernel).
    void* accptr = nullptr;
    cudaGetSymbolAddress(&accptr, g_acc);
    cudaMemsetAsync(accptr, 0, (size_t)N * 9 * sizeof(float));

    pair_kernel<<<NBLK, TPB>>>(params, iw1, ib1, ig1, ibt1, iw2, ib2);
    final_kernel<<<N / 8, TPB>>>(ow1, ob1, og1, obt1, ow2, ob2, out);
}